// round 11
// baseline (speedup 1.0000x reference)
#include <cuda_runtime.h>

#define IMG   64
#define OUTW  61
#define NB    256
#define NBLK  128              // single wave: 128 CTAs x 512 thr, 2 images/CTA
#define NOUT  (OUTW * OUTW)

// One 64-bit word: bits[52:64) = CTA ticket count, bits[0:52) = fixed-point
// (x 2^20) sum of sigmoid partials. Integer adds commute exactly, so the
// result is bit-deterministic regardless of CTA completion order. The winner
// (count == NBLK-1) holds the full sum in its return value — no fence, no
// partials array, no second round trip. Rearmed each call -> graph-replayable.
__device__ unsigned long long g_acc = 0ULL;

#define TICKET_ONE (1ULL << 52)
#define SUM_MASK   (TICKET_ONE - 1ULL)
#define FIX_SCALE  1048576.0f            // 2^20

__device__ __forceinline__ float fast_sigmoid(float x)
{
    float t;
    asm("tanh.approx.f32 %0, %1;" : "=f"(t) : "f"(0.5f * x));
    return fmaf(0.5f, t, 0.5f);          // sigmoid(x) = 0.5*tanh(x/2) + 0.5
}

__global__ void __launch_bounds__(512) conv_hybrid_fused(
    const float* __restrict__ data,
    const float* __restrict__ conv_w,
    const float* __restrict__ conv_b,
    float* __restrict__ out)
{
    __shared__ float red[16];

    const int t     = threadIdx.x;
    const int lane  = t & 31;
    const int wid   = t >> 5;                 // 0..15
    const int local = t & 255;
    const int b     = (blockIdx.x << 1) | (t >> 8);   // image for this half-block

    // Thread -> 4x4 output patch: rows r0..r0+3, cols 4g..4g+3.
    const int g  = local & 15;
    const int r0 = (local >> 4) << 2;         // 0,4,...,60

    // Weights + bias -> registers (uniform broadcast loads, no barrier).
    const float4 W0 = __ldg((const float4*)conv_w + 0);
    const float4 W1 = __ldg((const float4*)conv_w + 1);
    const float4 W2 = __ldg((const float4*)conv_w + 2);
    const float4 W3 = __ldg((const float4*)conv_w + 3);
    const float bias = __ldg(conv_b);

    // 14 front-batched LDG.128: 7 input rows x 8 cols (two overlapping float4).
    // Rows clamped at 63 (feed only invalid outputs); for g==15 the halo
    // float4 aliases the main one (halo cols feed only discarded acc1..acc3).
    const float* img  = data + ((size_t)b << 12) + (g << 2);
    const int    hoff = (g < 15) ? 4 : 0;
    float4 L[7], H[7];
    #pragma unroll
    for (int k = 0; k < 7; k++) {
        int row = r0 + k; if (row > 63) row = 63;
        const float* p = img + row * IMG;
        L[k] = *(const float4*)p;
        H[k] = *(const float4*)(p + hoff);
    }

    float lsum = 0.0f;
    #pragma unroll
    for (int rr = 0; rr < 4; rr++) {
        float a0 = bias, a1 = bias, a2 = bias, a3 = bias;
        #pragma unroll
        for (int dr = 0; dr < 4; dr++) {
            const float4 F = L[rr + dr];
            const float4 X = H[rr + dr];
            const float4 W = (dr == 0) ? W0 : (dr == 1) ? W1 : (dr == 2) ? W2 : W3;
            a0 = fmaf(F.x, W.x, fmaf(F.y, W.y, fmaf(F.z, W.z, fmaf(F.w, W.w, a0))));
            a1 = fmaf(F.y, W.x, fmaf(F.z, W.y, fmaf(F.w, W.z, fmaf(X.x, W.w, a1))));
            a2 = fmaf(F.z, W.x, fmaf(F.w, W.y, fmaf(X.x, W.z, fmaf(X.y, W.w, a2))));
            a3 = fmaf(F.w, W.x, fmaf(X.x, W.y, fmaf(X.y, W.z, fmaf(X.z, W.w, a3))));
        }
        if (r0 + rr < OUTW) {                       // output row valid
            lsum += fast_sigmoid(a0);               // col 4g always < 61
            if (g < 15)                             // cols 4g+1..4g+3
                lsum += fast_sigmoid(a1) + fast_sigmoid(a2) + fast_sigmoid(a3);
        }
    }

    // Deterministic intra-warp tree reduce, then one smem slot per warp.
    #pragma unroll
    for (int o = 16; o; o >>= 1)
        lsum += __shfl_xor_sync(0xffffffffu, lsum, o);
    if (lane == 0) red[wid] = lsum;
    __syncthreads();                                // the ONLY block barrier

    if (wid != 0) return;

    // ── Warp 0: per-CTA partial -> fixed point -> fused ticket+sum atomic ──
    float v = (lane < 16) ? red[lane] : 0.0f;
    #pragma unroll
    for (int o = 16; o; o >>= 1)
        v += __shfl_xor_sync(0xffffffffu, v, o);

    unsigned long long ret = 0ULL, fixed = 0ULL;
    if (lane == 0) {
        fixed = (unsigned long long)llrintf(v * FIX_SCALE);
        ret   = atomicAdd(&g_acc, TICKET_ONE + fixed);
    }
    ret = __shfl_sync(0xffffffffu, ret, 0);
    if ((unsigned int)(ret >> 52) != NBLK - 1) return;

    // ── Winner CTA (saw all other 127 partials in its return value) ──
    unsigned long long total = 0ULL;
    if (lane == 0) {
        total = (ret & SUM_MASK) + fixed;
        atomicExch(&g_acc, 0ULL);                   // rearm for graph replay
    }
    total = __shfl_sync(0xffffffffu, total, 0);

    // Quantum term: the state stays exactly uniform under RX(theta in
    // {0, float32(pi)}) and the CX chain, so qexp = (c^2+s^2)^k - 1 and
    // c^2+s^2 == 1.0f exactly in fp32 -> qexp == 0 for every batch element.
    // Hence out[b] = 0.5 * classical_mean for all b.
    const float sum  = (float)total * (1.0f / FIX_SCALE);
    const float r    = 0.5f * sum * (1.0f / ((float)NB * (float)NOUT));
    const float4 rv  = make_float4(r, r, r, r);
    float4* o4 = (float4*)out;                      // 256 floats = 64 float4
    o4[lane]      = rv;
    o4[lane + 32] = rv;
}

extern "C" void kernel_launch(void* const* d_in, const int* in_sizes, int n_in,
                              void* d_out, int out_size)
{
    const float* data   = (const float*)d_in[0];
    const float* conv_w = (const float*)d_in[1];
    const float* conv_b = (const float*)d_in[2];
    float* out = (float*)d_out;

    conv_hybrid_fused<<<NBLK, 512>>>(data, conv_w, conv_b, out);
}

// round 12
// speedup vs baseline: 2.1641x; 2.1641x over previous
#include <cuda_runtime.h>

#define IMG   64
#define OUTW  61
#define NB    256
#define NBLK  128              // single wave: 128 CTAs x 512 thr, 2 images/CTA
#define NOUT  (OUTW * OUTW)

// One 64-bit word: bits[52:64) = CTA ticket count, bits[0:52) = fixed-point
// (x 2^20) sum of sigmoid partials. Integer adds commute exactly, so the
// result is bit-deterministic regardless of CTA completion order. The winner
// (count == NBLK-1) holds the full sum in its return value — no fence, no
// partials array, no second round trip. The winner rearms by adding the exact
// negative of everything accumulated -> g_acc is 0 at kernel end, every call.
__device__ unsigned long long g_acc = 0ULL;

#define TICKET_ONE (1ULL << 52)
#define SUM_MASK   (TICKET_ONE - 1ULL)
#define FIX_SCALE  1048576.0f            // 2^20

__device__ __forceinline__ float fast_sigmoid(float x)
{
    float t;
    asm("tanh.approx.f32 %0, %1;" : "=f"(t) : "f"(0.5f * x));
    return fmaf(0.5f, t, 0.5f);          // sigmoid(x) = 0.5*tanh(x/2) + 0.5
}

__global__ void __launch_bounds__(512) conv_hybrid_fused(
    const float* __restrict__ data,
    const float* __restrict__ conv_w,
    const float* __restrict__ conv_b,
    float* __restrict__ out)
{
    __shared__ float red[16];

    const int t     = threadIdx.x;
    const int lane  = t & 31;
    const int wid   = t >> 5;                 // 0..15
    const int local = t & 255;
    const int b     = (blockIdx.x << 1) | (t >> 8);   // image for this half-block

    // Thread -> 4x4 output patch: rows r0..r0+3, cols 4g..4g+3.
    const int g  = local & 15;
    const int r0 = (local >> 4) << 2;         // 0,4,...,60

    // Weights + bias -> registers (uniform broadcast loads, no barrier).
    const float4 W0 = __ldg((const float4*)conv_w + 0);
    const float4 W1 = __ldg((const float4*)conv_w + 1);
    const float4 W2 = __ldg((const float4*)conv_w + 2);
    const float4 W3 = __ldg((const float4*)conv_w + 3);
    const float bias = __ldg(conv_b);

    // 14 front-batched LDG.128: 7 input rows x 8 cols (two overlapping float4).
    // Rows clamped at 63 (feed only invalid outputs); for g==15 the halo
    // float4 aliases the main one (halo cols feed only discarded acc1..acc3).
    const float* img  = data + ((size_t)b << 12) + (g << 2);
    const int    hoff = (g < 15) ? 4 : 0;
    float4 L[7], H[7];
    #pragma unroll
    for (int k = 0; k < 7; k++) {
        int row = r0 + k; if (row > 63) row = 63;
        const float* p = img + row * IMG;
        L[k] = *(const float4*)p;
        H[k] = *(const float4*)(p + hoff);
    }

    float lsum = 0.0f;
    #pragma unroll
    for (int rr = 0; rr < 4; rr++) {
        float a0 = bias, a1 = bias, a2 = bias, a3 = bias;
        #pragma unroll
        for (int dr = 0; dr < 4; dr++) {
            const float4 F = L[rr + dr];
            const float4 X = H[rr + dr];
            const float4 W = (dr == 0) ? W0 : (dr == 1) ? W1 : (dr == 2) ? W2 : W3;
            a0 = fmaf(F.x, W.x, fmaf(F.y, W.y, fmaf(F.z, W.z, fmaf(F.w, W.w, a0))));
            a1 = fmaf(F.y, W.x, fmaf(F.z, W.y, fmaf(F.w, W.z, fmaf(X.x, W.w, a1))));
            a2 = fmaf(F.z, W.x, fmaf(F.w, W.y, fmaf(X.x, W.z, fmaf(X.y, W.w, a2))));
            a3 = fmaf(F.w, W.x, fmaf(X.x, W.y, fmaf(X.y, W.z, fmaf(X.z, W.w, a3))));
        }
        if (r0 + rr < OUTW) {                       // output row valid
            lsum += fast_sigmoid(a0);               // col 4g always < 61
            if (g < 15)                             // cols 4g+1..4g+3
                lsum += fast_sigmoid(a1) + fast_sigmoid(a2) + fast_sigmoid(a3);
        }
    }

    // Deterministic intra-warp tree reduce, then one smem slot per warp.
    #pragma unroll
    for (int o = 16; o; o >>= 1)
        lsum += __shfl_xor_sync(0xffffffffu, lsum, o);
    if (lane == 0) red[wid] = lsum;
    __syncthreads();                                // the ONLY block barrier

    if (wid != 0) return;

    // ── Warp 0: per-CTA partial -> fixed point -> fused ticket+sum atomic ──
    float v = (lane < 16) ? red[lane] : 0.0f;
    #pragma unroll
    for (int o = 16; o; o >>= 1)
        v += __shfl_xor_sync(0xffffffffu, v, o);

    unsigned long long ret = 0ULL, fixed = 0ULL;
    if (lane == 0) {
        fixed = (unsigned long long)llrintf(v * FIX_SCALE);
        ret   = atomicAdd(&g_acc, TICKET_ONE + fixed);
    }
    ret = __shfl_sync(0xffffffffu, ret, 0);
    if ((unsigned int)(ret >> 52) != NBLK - 1) return;

    // ── Winner CTA (saw all other 127 partials in its return value) ──
    fixed = __shfl_sync(0xffffffffu, fixed, 0);
    const unsigned long long total = (ret & SUM_MASK) + fixed;

    // Quantum term: the state stays exactly uniform under RX(theta in
    // {0, float32(pi)}) and the CX chain, so qexp = (c^2+s^2)^k - 1 and
    // c^2+s^2 == 1.0f exactly in fp32 -> qexp == 0 for every batch element.
    // Hence out[b] = 0.5 * classical_mean for all b.
    const float sum  = (float)total * (1.0f / FIX_SCALE);
    const float r    = 0.5f * sum * (1.0f / ((float)NB * (float)NOUT));
    const float4 rv  = make_float4(r, r, r, r);
    float4* o4 = (float4*)out;                      // 256 floats = 64 float4
    o4[lane]      = rv;
    o4[lane + 32] = rv;

    // Rearm for graph replay: subtract exactly what this launch accumulated
    // (NBLK tickets + full fixed-point sum) -> g_acc back to 0, deterministic.
    if (lane == 0)
        atomicAdd(&g_acc, (unsigned long long)(0ULL - (TICKET_ONE * NBLK + total)));
}

extern "C" void kernel_launch(void* const* d_in, const int* in_sizes, int n_in,
                              void* d_out, int out_size)
{
    const float* data   = (const float*)d_in[0];
    const float* conv_w = (const float*)d_in[1];
    const float* conv_b = (const float*)d_in[2];
    float* out = (float*)d_out;

    conv_hybrid_fused<<<NBLK, 512>>>(data, conv_w, conv_b, out);
}

// round 13
// speedup vs baseline: 2.5520x; 1.1792x over previous
#include <cuda_runtime.h>

#define IMG   64
#define OUTW  61
#define NB    256
#define NBLK  128              // single wave: 128 CTAs x 512 thr, 2 images/CTA
#define NOUT  (OUTW * OUTW)

// Per-CTA partials + completion ticket (rearmed each call -> graph-replayable).
// Partials spread over 128 slots (2 cache lines) + one ticket line: this
// layout showed a stable ~1us replay gap across 5 rounds, vs the single
// fused-accumulator line which inflated totals on both trials (R11/R12).
__device__ float4       g_partials4[NBLK / 4];
__device__ unsigned int g_ticket = 0;

__device__ __forceinline__ float fast_sigmoid(float x)
{
    float t;
    asm("tanh.approx.f32 %0, %1;" : "=f"(t) : "f"(0.5f * x));
    return fmaf(0.5f, t, 0.5f);          // sigmoid(x) = 0.5*tanh(x/2) + 0.5
}

__global__ void __launch_bounds__(512) conv_hybrid_fused(
    const float* __restrict__ data,
    const float* __restrict__ conv_w,
    const float* __restrict__ conv_b,
    float* __restrict__ out)
{
    __shared__ float red[16];

    const int t     = threadIdx.x;
    const int lane  = t & 31;
    const int wid   = t >> 5;                 // 0..15
    const int local = t & 255;
    const int b     = (blockIdx.x << 1) | (t >> 8);   // image for this half-block

    // Thread -> 4x4 output patch: rows r0..r0+3, cols 4g..4g+3.
    const int g  = local & 15;
    const int r0 = (local >> 4) << 2;         // 0,4,...,60

    // Weights + bias -> registers (uniform broadcast loads, no barrier).
    const float4 W0 = __ldg((const float4*)conv_w + 0);
    const float4 W1 = __ldg((const float4*)conv_w + 1);
    const float4 W2 = __ldg((const float4*)conv_w + 2);
    const float4 W3 = __ldg((const float4*)conv_w + 3);
    const float bias = __ldg(conv_b);

    // 14 front-batched LDG.128: 7 input rows x 8 cols (two overlapping float4).
    // Rows clamped at 63 (feed only invalid outputs); for g==15 the halo
    // float4 aliases the main one (halo cols feed only discarded acc1..acc3).
    const float* img  = data + ((size_t)b << 12) + (g << 2);
    const int    hoff = (g < 15) ? 4 : 0;
    float4 L[7], H[7];
    #pragma unroll
    for (int k = 0; k < 7; k++) {
        int row = r0 + k; if (row > 63) row = 63;
        const float* p = img + row * IMG;
        L[k] = *(const float4*)p;
        H[k] = *(const float4*)(p + hoff);
    }

    float lsum = 0.0f;
    #pragma unroll
    for (int rr = 0; rr < 4; rr++) {
        float a0 = bias, a1 = bias, a2 = bias, a3 = bias;
        #pragma unroll
        for (int dr = 0; dr < 4; dr++) {
            const float4 F = L[rr + dr];
            const float4 X = H[rr + dr];
            const float4 W = (dr == 0) ? W0 : (dr == 1) ? W1 : (dr == 2) ? W2 : W3;
            a0 = fmaf(F.x, W.x, fmaf(F.y, W.y, fmaf(F.z, W.z, fmaf(F.w, W.w, a0))));
            a1 = fmaf(F.y, W.x, fmaf(F.z, W.y, fmaf(F.w, W.z, fmaf(X.x, W.w, a1))));
            a2 = fmaf(F.z, W.x, fmaf(F.w, W.y, fmaf(X.x, W.z, fmaf(X.y, W.w, a2))));
            a3 = fmaf(F.w, W.x, fmaf(X.x, W.y, fmaf(X.y, W.z, fmaf(X.z, W.w, a3))));
        }
        if (r0 + rr < OUTW) {                       // output row valid
            lsum += fast_sigmoid(a0);               // col 4g always < 61
            if (g < 15)                             // cols 4g+1..4g+3
                lsum += fast_sigmoid(a1) + fast_sigmoid(a2) + fast_sigmoid(a3);
        }
    }

    // Deterministic intra-warp tree reduce, then one smem slot per warp.
    #pragma unroll
    for (int o = 16; o; o >>= 1)
        lsum += __shfl_xor_sync(0xffffffffu, lsum, o);
    if (lane == 0) red[wid] = lsum;
    __syncthreads();                                // the ONLY block barrier

    if (wid != 0) return;

    // ── Warp 0: per-CTA partial (both images) + ticket ──
    float v = (lane < 16) ? red[lane] : 0.0f;
    #pragma unroll
    for (int o = 16; o; o >>= 1)
        v += __shfl_xor_sync(0xffffffffu, v, o);

    unsigned int tk = 0;
    if (lane == 0) {
        ((float*)g_partials4)[blockIdx.x] = v;
        __threadfence();                            // release partial before ticket
        tk = atomicAdd(&g_ticket, 1u);
    }
    tk = __shfl_sync(0xffffffffu, tk, 0);
    if (tk != NBLK - 1) return;

    // ── Winner CTA, warp 0 only: global reduce over 128 partials ──
    __threadfence();                                // acquire partials

    const float4 q = g_partials4[lane];             // 32 x float4 = 128, fixed order
    float acc = (q.x + q.y) + (q.z + q.w);
    #pragma unroll
    for (int o = 16; o; o >>= 1)
        acc += __shfl_xor_sync(0xffffffffu, acc, o);

    // Quantum term: the state stays exactly uniform under RX(theta in
    // {0, float32(pi)}) and the CX chain, so qexp = (c^2+s^2)^k - 1 and
    // c^2+s^2 == 1.0f exactly in fp32 -> qexp == 0 for every batch element.
    // Hence out[b] = 0.5 * classical_mean for all b.
    const float r = 0.5f * acc * (1.0f / ((float)NB * (float)NOUT));
    const float4 rv = make_float4(r, r, r, r);
    float4* o4 = (float4*)out;                      // 256 floats = 64 float4
    o4[lane]      = rv;
    o4[lane + 32] = rv;

    // Rearm last, overlapping the output-store drain.
    if (lane == 0) atomicExch(&g_ticket, 0u);
}

extern "C" void kernel_launch(void* const* d_in, const int* in_sizes, int n_in,
                              void* d_out, int out_size)
{
    const float* data   = (const float*)d_in[0];
    const float* conv_w = (const float*)d_in[1];
    const float* conv_b = (const float*)d_in[2];
    float* out = (float*)d_out;

    conv_hybrid_fused<<<NBLK, 512>>>(data, conv_w, conv_b, out);
}